// round 15
// baseline (speedup 1.0000x reference)
#include <cuda_runtime.h>
#include <cstdint>

#define LQ 64
#define DQ 128
#define EPSQ 1e-6f

// Precomputed: Vp = relu(W1)^T W2, Vn = min(W1,0)^T W2, Vb = 8*b2
__device__ __align__(16) float g_Vp[DQ];
__device__ __align__(16) float g_Vn[DQ];
__device__ __align__(16) float g_Vb[DQ];
__device__ int g_done = 0;   // monotone prep-completion counter (4 per run)
__device__ int g_nz   = 0;   // count of nonzero b1 entries (0 <=> fast path)

// ---- f32x2 packed helpers (Blackwell FFMA2; PTX-only) ----
__device__ __forceinline__ unsigned long long pk2(float x, float y) {
    unsigned long long r;
    asm("mov.b64 %0, {%1, %2};" : "=l"(r) : "f"(x), "f"(y));
    return r;
}
__device__ __forceinline__ unsigned long long fma2(
    unsigned long long a, unsigned long long b, unsigned long long c) {
    unsigned long long d;
    asm("fma.rn.f32x2 %0, %1, %2, %3;" : "=l"(d) : "l"(a), "l"(b), "l"(c));
    return d;
}

// ---- 32-id match mask via vcmpeq2 + PRMT flag-gather + signed DP4A pack ----
__device__ __forceinline__ unsigned mask32(const uint4* p4, unsigned myid2) {
    unsigned m = 0;
    #pragma unroll
    for (int k = 0; k < 4; ++k) {
        uint4 u = p4[k];
        unsigned pr0 = __byte_perm(__vcmpeq2(u.x, myid2), __vcmpeq2(u.y, myid2), 0x7531);
        unsigned pr1 = __byte_perm(__vcmpeq2(u.z, myid2), __vcmpeq2(u.w, myid2), 0x7531);
        int byte8 = __dp4a((int)pr1, (int)0x80C0E0F0,
                    __dp4a((int)pr0, (int)0xF8FCFEFF, 0));
        m |= ((unsigned)byte8) << (8 * k);
    }
    return m;
}

// ---------------------------------------------------------------------------
// Single fused kernel. Blocks 0-3 compute the V fold first (release via
// g_done), then do their sample like everyone else. All blocks do the
// V-independent phases, then acquire-wait on g_done before the store phase.
// ---------------------------------------------------------------------------
__global__ __launch_bounds__(256, 6)
void lpe_main_kernel(const int*   __restrict__ src_ids,
                     const int*   __restrict__ dst_ids,
                     const int*   __restrict__ src_nid,
                     const int*   __restrict__ dst_nid,
                     const float* __restrict__ itimes,
                     const float* __restrict__ src_t,
                     const float* __restrict__ dst_t,
                     const float* __restrict__ W1,
                     const float* __restrict__ b1,
                     const float* __restrict__ W2,
                     const float* __restrict__ b2,
                     float*       __restrict__ out,
                     int B) {
    __shared__ __align__(16) unsigned short s_ids16[2][LQ];
    __shared__ float s_t[2][LQ];
    __shared__ float s_avg[2][LQ];
    __shared__ float s_rec[2][LQ];
    __shared__ __align__(16) ulonglong2 s_S[128];   // packed (sp2, sn2) per pos
    __shared__ float s_rvp[8][32], s_rvn[8][32];    // prep reduce (blocks 0-3)
    __shared__ float s_feat[2][LQ][8];              // slow path only

    const int b   = blockIdx.x;
    const int tid = threadIdx.x;

    const float cur_t = __ldg(&itimes[b]);
    const int   snid  = __ldg(&src_nid[b]);
    const int   dnid  = __ldg(&dst_nid[b]);

    // ---- tile load: tid<128 -> ids (u16), tid>=128 -> times ----
    {
        int sd = (tid & 127) >> 6, p = tid & 63;
        if (tid < 128)
            s_ids16[sd][p] =
                (unsigned short)__ldg(&(sd ? dst_ids : src_ids)[b * LQ + p]);
        else
            s_t[sd][p] = __ldg(&(sd ? dst_t : src_t)[b * LQ + p]);
    }

    // ---- prep role (blocks 0-3): fold W1 through W2 for 32 e-columns ----
    if (b < 4) {
        const int el = tid & 31;
        const int dg = tid >> 5;
        const int e  = b * 32 + el;
        float vp = 0.f, vn = 0.f;
        #pragma unroll
        for (int k = 0; k < 16; ++k) {
            int d = dg * 16 + k;
            float w  = __ldg(&W1[d]);
            float w2 = __ldg(&W2[d * DQ + e]);
            vp = fmaf(fmaxf(w, 0.f), w2, vp);
            vn = fmaf(fminf(w, 0.f), w2, vn);
        }
        s_rvp[dg][el] = vp;
        s_rvn[dg][el] = vn;
        if (b == 0 && tid < DQ && __ldg(&b1[tid]) != 0.f) atomicAdd(&g_nz, 1);
        __syncthreads();
        if (dg == 0) {
            float sp = 0.f, sn = 0.f;
            #pragma unroll
            for (int g = 0; g < 8; ++g) { sp += s_rvp[g][el]; sn += s_rvn[g][el]; }
            g_Vp[e] = sp;
            g_Vn[e] = sn;
            g_Vb[e] = 8.f * __ldg(&b2[e]);
        }
        __syncthreads();
        __threadfence();
        if (tid == 0) atomicAdd(&g_done, 1);   // release
    }
    __syncthreads();

    const int half = tid & 1;
    const int pos  = tid >> 1;     // 0..127
    const int side = pos >> 6;     // warp-uniform
    const int i    = pos & 63;
    const int os   = side ^ 1;

    const int      myid  = s_ids16[side][i];
    const unsigned myid2 = (unsigned)myid * 0x00010001u;
    const float    myt   = s_t[side][i];

    // ---- mask build (V-independent) ----
    unsigned mo = mask32((const uint4*)&s_ids16[side][half << 5], myid2);
    unsigned mx = mask32((const uint4*)&s_ids16[os][half << 5],   myid2);
    unsigned long long m_own = ((unsigned long long)mo) << (half << 5);
    unsigned long long m_oth = ((unsigned long long)mx) << (half << 5);
    m_own |= __shfl_xor_sync(0xFFFFFFFFu, m_own, 1);
    m_oth |= __shfl_xor_sync(0xFFFFFFFFu, m_oth, 1);

    const int n     = __popcll(m_own);
    const int split = n >> 1;

    // ---- sparse group stats: half0 -> extrema, half1 -> t_split ----
    float tmax = -3.402823466e38f, tmin = 3.402823466e38f, ts = 0.f;
    if (!half) {
        unsigned long long m = m_own;
        while (m) {
            int j = __ffsll((long long)m) - 1;
            m &= m - 1;
            float tj = s_t[side][j];
            tmax = fmaxf(tmax, tj);
            tmin = fminf(tmin, tj);
        }
    } else if (n >= 4) {
        unsigned long long mc = m_own;
        while (mc) {
            int j = __ffsll((long long)mc) - 1;
            mc &= mc - 1;
            float tj = s_t[side][j];
            int r = 0;
            unsigned long long mi = m_own;
            while (mi) {
                int q = __ffsll((long long)mi) - 1;
                mi &= mi - 1;
                float tq = s_t[side][q];
                r += (tq < tj) || (tq == tj && q < j);
            }
            if (r == split) ts = tj;
        }
    }
    ts = __shfl_xor_sync(0xFFFFFFFFu, ts, 1) + ts;

    float my_avg = 0.f, my_rec = 0.f;
    if (!half) {
        float nf  = (float)n;
        my_avg = (n > 1) ? (tmax - tmin) / (nf - 1.f) : 0.f;
        float den = fmaxf(nf - (float)split - 1.f, 1.f);
        my_rec = (n >= 4) ? (tmax - ts) / den : 0.f;
        if (myid == 0) { my_avg = 0.f; my_rec = 0.f; }
        s_avg[side][i] = my_avg;
        s_rec[side][i] = my_rec;
    }

    // ---- acquire-wait for prep completion (usually already done) ----
    if (tid == 0) {
        while (atomicAdd(&g_done, 0) < 4) __nanosleep(32);
        __threadfence();
    }
    __syncthreads();   // also publishes s_avg/s_rec

    const int fast = (*(volatile int*)&g_nz) == 0;

    // ---- features (half0 lanes) -> packed (sp2, sn2) staged in smem ----
    float sp = 0.f, sn = 0.f;
    if (!half) {
        int other_node = side ? snid : dnid;

        int co = __popcll(m_oth);
        float lt = 0.f, iat_o = 0.f, riat_o = 0.f;
        if (m_oth) {
            int jf = __ffsll((long long)m_oth) - 1;
            int jl = 63 - __clzll((long long)m_oth);
            lt     = s_t[os][jl];
            iat_o  = s_avg[os][jf];
            riat_o = s_rec[os][jf];
        }

        float f0 = (float)n;
        float f1 = (float)co;
        float f2 = (myid == other_node) ? 1.f : 0.f;
        float f3 = (co > 0) ? 1.f : 0.f;
        float f4 = (co > 0) ? f0 / (f1 + EPSQ) : 0.f;
        float rcy_self  = cur_t - myt;
        float rcy_other = cur_t - lt;
        float f5 = (rcy_self > EPSQ) ? rcy_other / (rcy_self + EPSQ) : 0.f;
        float f6 = (iat_o  > EPSQ) ? my_avg / (iat_o  + EPSQ) : 0.f;
        float f7 = (riat_o > EPSQ) ? my_rec / (riat_o + EPSQ) : 0.f;
        if (myid == 0) { f0 = f1 = f2 = f3 = f4 = f5 = f6 = f7 = 0.f; }

        sp = fmaxf(f0,0.f)+fmaxf(f1,0.f)+fmaxf(f2,0.f)+fmaxf(f3,0.f)
           + fmaxf(f4,0.f)+fmaxf(f5,0.f)+fmaxf(f6,0.f)+fmaxf(f7,0.f);
        sn = fminf(f0,0.f)+fminf(f1,0.f)+fminf(f2,0.f)+fminf(f3,0.f)
           + fminf(f4,0.f)+fminf(f5,0.f)+fminf(f6,0.f)+fminf(f7,0.f);

        ulonglong2 s2;
        s2.x = pk2(sp, sp);
        s2.y = pk2(sn, sn);
        s_S[pos] = s2;                  // STS.128 into own warp's range

        if (!fast) {
            float* fp = &s_feat[side][i][0];
            fp[0]=f0; fp[1]=f1; fp[2]=f2; fp[3]=f3;
            fp[4]=f4; fp[5]=f5; fp[6]=f6; fp[7]=f7;
        }
    }
    __syncwarp();   // s_S rows for this warp written by its own even lanes

    if (fast) {
        // ---- per-warp store of its own 16 rows; 1 LDS.128/row scalar fetch ----
        const int w    = tid >> 5;
        const int lane = tid & 31;
        const int sdw  = w >> 2;
        const int lb   = (w & 3) << 4;

        const ulonglong2 vvp = __ldg((const ulonglong2*)g_Vp + lane);
        const ulonglong2 vvn = __ldg((const ulonglong2*)g_Vn + lane);
        const ulonglong2 vbb = __ldg((const ulonglong2*)g_Vb + lane);

        const ulonglong2* srow = &s_S[w * 16];
        ulonglong2* out2 = (ulonglong2*)out +
            (((size_t)sdw * B + b) * LQ + lb) * (DQ / 4);
        #pragma unroll
        for (int r = 0; r < 16; ++r) {
            ulonglong2 s2 = srow[r];    // LDS.128 broadcast
            ulonglong2 y;
            y.x = fma2(s2.x, vvp.x, fma2(s2.y, vvn.x, vbb.x));
            y.y = fma2(s2.x, vvp.y, fma2(s2.y, vvn.y, vbb.y));
            __stcs(&out2[r * 32 + lane], y);
        }
    } else {
        // ---- general-b1 path (never taken: dataset has b1 == 0) ----
        __syncthreads();
        __shared__ float sW1[DQ], sb1[DQ];
        if (tid < DQ) { sW1[tid] = W1[tid]; sb1[tid] = b1[tid]; }
        __syncthreads();
        const size_t sideStride = (size_t)B * (LQ * DQ);
        for (int wdx = tid; wdx < 2 * LQ * DQ; wdx += 256) {
            int e    = wdx & 127;
            int row  = wdx >> 7;
            int sd   = row >> 6, l = row & 63;
            float y = 8.f * __ldg(&b2[e]);
            #pragma unroll
            for (int f = 0; f < 8; ++f) {
                float fv  = s_feat[sd][l][f];
                float acc = 0.f;
                for (int d = 0; d < DQ; ++d) {
                    float h = fmaxf(fmaf(fv, sW1[d], sb1[d]), 0.f);
                    acc = fmaf(h, __ldg(&W2[d * DQ + e]), acc);
                }
                y += acc;
            }
            out[(size_t)sd * sideStride + (size_t)b * (LQ * DQ) + (size_t)l * DQ + e] = y;
        }
    }
}

// ---------------------------------------------------------------------------
extern "C" void kernel_launch(void* const* d_in, const int* in_sizes, int n_in,
                              void* d_out, int out_size) {
    const int*   src_ids = (const int*)  d_in[0];
    const int*   dst_ids = (const int*)  d_in[1];
    const int*   src_nid = (const int*)  d_in[2];
    const int*   dst_nid = (const int*)  d_in[3];
    const float* itimes  = (const float*)d_in[4];
    const float* src_t   = (const float*)d_in[5];
    const float* dst_t   = (const float*)d_in[6];
    const float* W1      = (const float*)d_in[7];
    const float* b1      = (const float*)d_in[8];
    const float* W2      = (const float*)d_in[9];
    const float* b2      = (const float*)d_in[10];
    float* out = (float*)d_out;
    int B = in_sizes[2];  // src_node_ids count

    lpe_main_kernel<<<B, 256>>>(src_ids, dst_ids, src_nid, dst_nid,
                                itimes, src_t, dst_t,
                                W1, b1, W2, b2, out, B);
}

// round 16
// speedup vs baseline: 1.0550x; 1.0550x over previous
#include <cuda_runtime.h>
#include <cstdint>

#define LQ 64
#define DQ 128
#define EPSQ 1e-6f

// Precomputed: Vp = relu(W1)^T W2, Vn = min(W1,0)^T W2, Vb = 8*b2
__device__ __align__(16) float g_Vp[DQ];
__device__ __align__(16) float g_Vn[DQ];
__device__ __align__(16) float g_Vb[DQ];
__device__ int   g_b1_zero;

// ---- f32x2 packed helpers (Blackwell FFMA2; PTX-only) ----
__device__ __forceinline__ unsigned long long pk2(float x, float y) {
    unsigned long long r;
    asm("mov.b64 %0, {%1, %2};" : "=l"(r) : "f"(x), "f"(y));
    return r;
}
__device__ __forceinline__ unsigned long long fma2(
    unsigned long long a, unsigned long long b, unsigned long long c) {
    unsigned long long d;
    asm("fma.rn.f32x2 %0, %1, %2, %3;" : "=l"(d) : "l"(a), "l"(b), "l"(c));
    return d;
}

// ---- 32-id match mask via vcmpeq2 + PRMT flag-gather + signed DP4A pack ----
__device__ __forceinline__ unsigned mask32(const uint4* p4, unsigned myid2) {
    unsigned m = 0;
    #pragma unroll
    for (int k = 0; k < 4; ++k) {
        uint4 u = p4[k];
        unsigned pr0 = __byte_perm(__vcmpeq2(u.x, myid2), __vcmpeq2(u.y, myid2), 0x7531);
        unsigned pr1 = __byte_perm(__vcmpeq2(u.z, myid2), __vcmpeq2(u.w, myid2), 0x7531);
        int byte8 = __dp4a((int)pr1, (int)0x80C0E0F0,
                    __dp4a((int)pr0, (int)0xF8FCFEFF, 0));
        m |= ((unsigned)byte8) << (8 * k);
    }
    return m;
}

// ---------------------------------------------------------------------------
__global__ __launch_bounds__(256)
void prep_kernel(const float* __restrict__ W1,
                 const float* __restrict__ b1,
                 const float* __restrict__ W2,
                 const float* __restrict__ b2) {
    __shared__ float rvp[8][32];
    __shared__ float rvn[8][32];
    __shared__ int nz;
    const int t  = threadIdx.x;
    const int el = t & 31;
    const int dg = t >> 5;
    const int e  = blockIdx.x * 32 + el;

    if (t == 0) nz = 0;
    __syncthreads();

    float vp = 0.f, vn = 0.f;
    #pragma unroll
    for (int k = 0; k < 16; ++k) {
        int d = dg * 16 + k;
        float w  = __ldg(&W1[d]);
        float w2 = __ldg(&W2[d * DQ + e]);
        vp = fmaf(fmaxf(w, 0.f), w2, vp);
        vn = fmaf(fminf(w, 0.f), w2, vn);
    }
    rvp[dg][el] = vp;
    rvn[dg][el] = vn;

    if (blockIdx.x == 0 && t < DQ && b1[t] != 0.f) atomicAdd(&nz, 1);
    __syncthreads();

    if (dg == 0) {
        float sp = 0.f, sn = 0.f;
        #pragma unroll
        for (int g = 0; g < 8; ++g) { sp += rvp[g][el]; sn += rvn[g][el]; }
        g_Vp[e] = sp;
        g_Vn[e] = sn;
        g_Vb[e] = 8.f * __ldg(&b2[e]);
    }
    __syncthreads();
    if (blockIdx.x == 0 && t == 0) g_b1_zero = (nz == 0) ? 1 : 0;
}

// ---------------------------------------------------------------------------
// Main: one block per sample (R14 structure). Store-loop scalar fetch via
// smem-staged packed (sp2, sn2): even lanes STS.128 once, store loop does one
// broadcast LDS.128 per row instead of 2 SHFL + 2 pk2.
// ---------------------------------------------------------------------------
__global__ __launch_bounds__(256, 6)
void lpe_main_kernel(const int*   __restrict__ src_ids,
                     const int*   __restrict__ dst_ids,
                     const int*   __restrict__ src_nid,
                     const int*   __restrict__ dst_nid,
                     const float* __restrict__ itimes,
                     const float* __restrict__ src_t,
                     const float* __restrict__ dst_t,
                     const float* __restrict__ W1,
                     const float* __restrict__ b1,
                     const float* __restrict__ W2,
                     const float* __restrict__ b2,
                     float*       __restrict__ out,
                     int B) {
    __shared__ __align__(16) unsigned short s_ids16[2][LQ];  // ids < 512
    __shared__ float s_t[2][LQ];
    __shared__ float s_avg[2][LQ];
    __shared__ float s_rec[2][LQ];
    __shared__ __align__(16) ulonglong2 s_S[128];   // packed (sp2, sn2) per pos
    __shared__ float s_feat[2][LQ][8];   // slow path only

    const int b   = blockIdx.x;
    const int tid = threadIdx.x;

    const float cur_t = __ldg(&itimes[b]);
    const int   snid  = __ldg(&src_nid[b]);
    const int   dnid  = __ldg(&dst_nid[b]);

    // ---- load tile: tid<128 -> ids (as u16), tid>=128 -> times ----
    {
        int sd = (tid & 127) >> 6, p = tid & 63;
        if (tid < 128)
            s_ids16[sd][p] =
                (unsigned short)__ldg(&(sd ? dst_ids : src_ids)[b * LQ + p]);
        else
            s_t[sd][p] = __ldg(&(sd ? dst_t : src_t)[b * LQ + p]);
    }
    __syncthreads();

    const int fast = g_b1_zero;

    const int half = tid & 1;
    const int pos  = tid >> 1;     // 0..127
    const int side = pos >> 6;     // warp-uniform
    const int i    = pos & 63;
    const int os   = side ^ 1;

    const int      myid  = s_ids16[side][i];
    const unsigned myid2 = (unsigned)myid * 0x00010001u;  // duplicated halves
    const float    myt   = s_t[side][i];

    // ---- mask build: 8 ids per LDS.128, dp4a-packed flags ----
    unsigned mo = mask32((const uint4*)&s_ids16[side][half << 5], myid2);
    unsigned mx = mask32((const uint4*)&s_ids16[os][half << 5],   myid2);
    unsigned long long m_own = ((unsigned long long)mo) << (half << 5);
    unsigned long long m_oth = ((unsigned long long)mx) << (half << 5);
    m_own |= __shfl_xor_sync(0xFFFFFFFFu, m_own, 1);
    m_oth |= __shfl_xor_sync(0xFFFFFFFFu, m_oth, 1);

    const int n     = __popcll(m_own);
    const int split = n >> 1;

    // ---- sparse group stats: half0 -> extrema, half1 -> t_split ----
    float tmax = -3.402823466e38f, tmin = 3.402823466e38f, ts = 0.f;
    if (!half) {
        unsigned long long m = m_own;
        while (m) {
            int j = __ffsll((long long)m) - 1;
            m &= m - 1;
            float tj = s_t[side][j];
            tmax = fmaxf(tmax, tj);
            tmin = fminf(tmin, tj);
        }
    } else if (n >= 4) {
        unsigned long long mc = m_own;
        while (mc) {
            int j = __ffsll((long long)mc) - 1;
            mc &= mc - 1;
            float tj = s_t[side][j];
            int r = 0;
            unsigned long long mi = m_own;
            while (mi) {
                int q = __ffsll((long long)mi) - 1;
                mi &= mi - 1;
                float tq = s_t[side][q];
                r += (tq < tj) || (tq == tj && q < j);
            }
            if (r == split) ts = tj;
        }
    }
    ts = __shfl_xor_sync(0xFFFFFFFFu, ts, 1) + ts;

    float my_avg = 0.f, my_rec = 0.f;
    if (!half) {
        float nf  = (float)n;
        my_avg = (n > 1) ? (tmax - tmin) / (nf - 1.f) : 0.f;
        float den = fmaxf(nf - (float)split - 1.f, 1.f);
        my_rec = (n >= 4) ? (tmax - ts) / den : 0.f;
        if (myid == 0) { my_avg = 0.f; my_rec = 0.f; }
        s_avg[side][i] = my_avg;
        s_rec[side][i] = my_rec;
    }
    __syncthreads();

    // ---- features (half0 lanes) -> packed (sp2, sn2) staged in smem ----
    if (!half) {
        int other_node = side ? snid : dnid;

        int co = __popcll(m_oth);
        float lt = 0.f, iat_o = 0.f, riat_o = 0.f;
        if (m_oth) {
            int jf = __ffsll((long long)m_oth) - 1;
            int jl = 63 - __clzll((long long)m_oth);
            lt     = s_t[os][jl];
            iat_o  = s_avg[os][jf];
            riat_o = s_rec[os][jf];
        }

        float f0 = (float)n;
        float f1 = (float)co;
        float f2 = (myid == other_node) ? 1.f : 0.f;
        float f3 = (co > 0) ? 1.f : 0.f;
        float f4 = (co > 0) ? f0 / (f1 + EPSQ) : 0.f;
        float rcy_self  = cur_t - myt;
        float rcy_other = cur_t - lt;
        float f5 = (rcy_self > EPSQ) ? rcy_other / (rcy_self + EPSQ) : 0.f;
        float f6 = (iat_o  > EPSQ) ? my_avg / (iat_o  + EPSQ) : 0.f;
        float f7 = (riat_o > EPSQ) ? my_rec / (riat_o + EPSQ) : 0.f;
        if (myid == 0) { f0 = f1 = f2 = f3 = f4 = f5 = f6 = f7 = 0.f; }

        float sp = fmaxf(f0,0.f)+fmaxf(f1,0.f)+fmaxf(f2,0.f)+fmaxf(f3,0.f)
                 + fmaxf(f4,0.f)+fmaxf(f5,0.f)+fmaxf(f6,0.f)+fmaxf(f7,0.f);
        float sn = fminf(f0,0.f)+fminf(f1,0.f)+fminf(f2,0.f)+fminf(f3,0.f)
                 + fminf(f4,0.f)+fminf(f5,0.f)+fminf(f6,0.f)+fminf(f7,0.f);

        ulonglong2 s2;
        s2.x = pk2(sp, sp);
        s2.y = pk2(sn, sn);
        s_S[pos] = s2;                  // STS.128 into own warp's range

        if (!fast) {
            float* fp = &s_feat[side][i][0];
            fp[0]=f0; fp[1]=f1; fp[2]=f2; fp[3]=f3;
            fp[4]=f4; fp[5]=f5; fp[6]=f6; fp[7]=f7;
        }
    }
    __syncwarp();   // s_S rows for this warp written by its own even lanes

    if (fast) {
        // ---- per-warp store of its own 16 rows; 1 LDS.128/row scalar fetch ----
        const int w    = tid >> 5;          // 0..7
        const int lane = tid & 31;
        const int sdw  = w >> 2;
        const int lb   = (w & 3) << 4;

        const ulonglong2 vvp = __ldg((const ulonglong2*)g_Vp + lane);
        const ulonglong2 vvn = __ldg((const ulonglong2*)g_Vn + lane);
        const ulonglong2 vbb = __ldg((const ulonglong2*)g_Vb + lane);

        const ulonglong2* srow = &s_S[w * 16];
        ulonglong2* out2 = (ulonglong2*)out +
            (((size_t)sdw * B + b) * LQ + lb) * (DQ / 4);
        #pragma unroll
        for (int r = 0; r < 16; ++r) {
            ulonglong2 s2 = srow[r];    // LDS.128 broadcast
            ulonglong2 y;
            y.x = fma2(s2.x, vvp.x, fma2(s2.y, vvn.x, vbb.x));
            y.y = fma2(s2.x, vvp.y, fma2(s2.y, vvn.y, vbb.y));
            __stcs(&out2[r * 32 + lane], y);
        }
    } else {
        // ---- general-b1 path (never taken: dataset has b1 == 0) ----
        __syncthreads();
        __shared__ float sW1[DQ], sb1[DQ];
        if (tid < DQ) { sW1[tid] = W1[tid]; sb1[tid] = b1[tid]; }
        __syncthreads();
        const size_t sideStride = (size_t)B * (LQ * DQ);
        for (int wdx = tid; wdx < 2 * LQ * DQ; wdx += 256) {
            int e    = wdx & 127;
            int row  = wdx >> 7;
            int sd   = row >> 6, l = row & 63;
            float y = 8.f * __ldg(&b2[e]);
            #pragma unroll
            for (int f = 0; f < 8; ++f) {
                float fv  = s_feat[sd][l][f];
                float acc = 0.f;
                for (int d = 0; d < DQ; ++d) {
                    float h = fmaxf(fmaf(fv, sW1[d], sb1[d]), 0.f);
                    acc = fmaf(h, __ldg(&W2[d * DQ + e]), acc);
                }
                y += acc;
            }
            out[(size_t)sd * sideStride + (size_t)b * (LQ * DQ) + (size_t)l * DQ + e] = y;
        }
    }
}

// ---------------------------------------------------------------------------
extern "C" void kernel_launch(void* const* d_in, const int* in_sizes, int n_in,
                              void* d_out, int out_size) {
    const int*   src_ids = (const int*)  d_in[0];
    const int*   dst_ids = (const int*)  d_in[1];
    const int*   src_nid = (const int*)  d_in[2];
    const int*   dst_nid = (const int*)  d_in[3];
    const float* itimes  = (const float*)d_in[4];
    const float* src_t   = (const float*)d_in[5];
    const float* dst_t   = (const float*)d_in[6];
    const float* W1      = (const float*)d_in[7];
    const float* b1      = (const float*)d_in[8];
    const float* W2      = (const float*)d_in[9];
    const float* b2      = (const float*)d_in[10];
    float* out = (float*)d_out;
    int B = in_sizes[2];  // src_node_ids count

    prep_kernel<<<4, 256>>>(W1, b1, W2, b2);
    lpe_main_kernel<<<B, 256>>>(src_ids, dst_ids, src_nid, dst_nid,
                                itimes, src_t, dst_t,
                                W1, b1, W2, b2, out, B);
}

// round 17
// speedup vs baseline: 1.0649x; 1.0094x over previous
#include <cuda_runtime.h>
#include <cstdint>

#define LQ 64
#define DQ 128
#define EPSQ 1e-6f

// Precomputed: Vp = relu(W1)^T W2, Vn = min(W1,0)^T W2, Vb = 8*b2
__device__ __align__(16) float g_Vp[DQ];
__device__ __align__(16) float g_Vn[DQ];
__device__ __align__(16) float g_Vb[DQ];
__device__ int   g_b1_zero;

// ---- f32x2 packed helpers (Blackwell FFMA2; PTX-only) ----
__device__ __forceinline__ unsigned long long pk2(float x, float y) {
    unsigned long long r;
    asm("mov.b64 %0, {%1, %2};" : "=l"(r) : "f"(x), "f"(y));
    return r;
}
__device__ __forceinline__ unsigned long long fma2(
    unsigned long long a, unsigned long long b, unsigned long long c) {
    unsigned long long d;
    asm("fma.rn.f32x2 %0, %1, %2, %3;" : "=l"(d) : "l"(a), "l"(b), "l"(c));
    return d;
}

// ---- 32-id match mask via vcmpeq2 + PRMT flag-gather + signed DP4A pack ----
__device__ __forceinline__ unsigned mask32(const uint4* p4, unsigned myid2) {
    unsigned m = 0;
    #pragma unroll
    for (int k = 0; k < 4; ++k) {
        uint4 u = p4[k];
        unsigned pr0 = __byte_perm(__vcmpeq2(u.x, myid2), __vcmpeq2(u.y, myid2), 0x7531);
        unsigned pr1 = __byte_perm(__vcmpeq2(u.z, myid2), __vcmpeq2(u.w, myid2), 0x7531);
        int byte8 = __dp4a((int)pr1, (int)0x80C0E0F0,
                    __dp4a((int)pr0, (int)0xF8FCFEFF, 0));
        m |= ((unsigned)byte8) << (8 * k);
    }
    return m;
}

// ---------------------------------------------------------------------------
__global__ __launch_bounds__(256)
void prep_kernel(const float* __restrict__ W1,
                 const float* __restrict__ b1,
                 const float* __restrict__ W2,
                 const float* __restrict__ b2) {
    __shared__ float rvp[8][32];
    __shared__ float rvn[8][32];
    __shared__ int nz;
    const int t  = threadIdx.x;
    const int el = t & 31;
    const int dg = t >> 5;
    const int e  = blockIdx.x * 32 + el;

    if (t == 0) nz = 0;
    __syncthreads();

    float vp = 0.f, vn = 0.f;
    #pragma unroll
    for (int k = 0; k < 16; ++k) {
        int d = dg * 16 + k;
        float w  = __ldg(&W1[d]);
        float w2 = __ldg(&W2[d * DQ + e]);
        vp = fmaf(fmaxf(w, 0.f), w2, vp);
        vn = fmaf(fminf(w, 0.f), w2, vn);
    }
    rvp[dg][el] = vp;
    rvn[dg][el] = vn;

    if (blockIdx.x == 0 && t < DQ && b1[t] != 0.f) atomicAdd(&nz, 1);
    __syncthreads();

    if (dg == 0) {
        float sp = 0.f, sn = 0.f;
        #pragma unroll
        for (int g = 0; g < 8; ++g) { sp += rvp[g][el]; sn += rvn[g][el]; }
        g_Vp[e] = sp;
        g_Vn[e] = sn;
        g_Vb[e] = 8.f * __ldg(&b2[e]);
    }
    __syncthreads();
    if (blockIdx.x == 0 && t == 0) g_b1_zero = (nz == 0) ? 1 : 0;
}

// ---------------------------------------------------------------------------
// Main: one block per sample (R16 structure) with fast-division feature math
// (__fdividef: MUFU.RCP + FMUL, rel err ~2^-22 << 1e-3 tolerance).
// ---------------------------------------------------------------------------
__global__ __launch_bounds__(256, 6)
void lpe_main_kernel(const int*   __restrict__ src_ids,
                     const int*   __restrict__ dst_ids,
                     const int*   __restrict__ src_nid,
                     const int*   __restrict__ dst_nid,
                     const float* __restrict__ itimes,
                     const float* __restrict__ src_t,
                     const float* __restrict__ dst_t,
                     const float* __restrict__ W1,
                     const float* __restrict__ b1,
                     const float* __restrict__ W2,
                     const float* __restrict__ b2,
                     float*       __restrict__ out,
                     int B) {
    __shared__ __align__(16) unsigned short s_ids16[2][LQ];  // ids < 512
    __shared__ float s_t[2][LQ];
    __shared__ float s_avg[2][LQ];
    __shared__ float s_rec[2][LQ];
    __shared__ __align__(16) ulonglong2 s_S[128];   // packed (sp2, sn2) per pos
    __shared__ float s_feat[2][LQ][8];   // slow path only

    const int b   = blockIdx.x;
    const int tid = threadIdx.x;

    const float cur_t = __ldg(&itimes[b]);
    const int   snid  = __ldg(&src_nid[b]);
    const int   dnid  = __ldg(&dst_nid[b]);

    // ---- load tile: tid<128 -> ids (as u16), tid>=128 -> times ----
    {
        int sd = (tid & 127) >> 6, p = tid & 63;
        if (tid < 128)
            s_ids16[sd][p] =
                (unsigned short)__ldg(&(sd ? dst_ids : src_ids)[b * LQ + p]);
        else
            s_t[sd][p] = __ldg(&(sd ? dst_t : src_t)[b * LQ + p]);
    }
    __syncthreads();

    const int fast = g_b1_zero;

    const int half = tid & 1;
    const int pos  = tid >> 1;     // 0..127
    const int side = pos >> 6;     // warp-uniform
    const int i    = pos & 63;
    const int os   = side ^ 1;

    const int      myid  = s_ids16[side][i];
    const unsigned myid2 = (unsigned)myid * 0x00010001u;  // duplicated halves
    const float    myt   = s_t[side][i];

    // ---- mask build: 8 ids per LDS.128, dp4a-packed flags ----
    unsigned mo = mask32((const uint4*)&s_ids16[side][half << 5], myid2);
    unsigned mx = mask32((const uint4*)&s_ids16[os][half << 5],   myid2);
    unsigned long long m_own = ((unsigned long long)mo) << (half << 5);
    unsigned long long m_oth = ((unsigned long long)mx) << (half << 5);
    m_own |= __shfl_xor_sync(0xFFFFFFFFu, m_own, 1);
    m_oth |= __shfl_xor_sync(0xFFFFFFFFu, m_oth, 1);

    const int n     = __popcll(m_own);
    const int split = n >> 1;

    // ---- sparse group stats: half0 -> extrema, half1 -> t_split ----
    float tmax = -3.402823466e38f, tmin = 3.402823466e38f, ts = 0.f;
    if (!half) {
        unsigned long long m = m_own;
        while (m) {
            int j = __ffsll((long long)m) - 1;
            m &= m - 1;
            float tj = s_t[side][j];
            tmax = fmaxf(tmax, tj);
            tmin = fminf(tmin, tj);
        }
    } else if (n >= 4) {
        unsigned long long mc = m_own;
        while (mc) {
            int j = __ffsll((long long)mc) - 1;
            mc &= mc - 1;
            float tj = s_t[side][j];
            int r = 0;
            unsigned long long mi = m_own;
            while (mi) {
                int q = __ffsll((long long)mi) - 1;
                mi &= mi - 1;
                float tq = s_t[side][q];
                r += (tq < tj) || (tq == tj && q < j);
            }
            if (r == split) ts = tj;
        }
    }
    ts = __shfl_xor_sync(0xFFFFFFFFu, ts, 1) + ts;

    float my_avg = 0.f, my_rec = 0.f;
    if (!half) {
        float nf  = (float)n;
        my_avg = (n > 1) ? __fdividef(tmax - tmin, nf - 1.f) : 0.f;
        float den = fmaxf(nf - (float)split - 1.f, 1.f);
        my_rec = (n >= 4) ? __fdividef(tmax - ts, den) : 0.f;
        if (myid == 0) { my_avg = 0.f; my_rec = 0.f; }
        s_avg[side][i] = my_avg;
        s_rec[side][i] = my_rec;
    }
    __syncthreads();

    // ---- features (half0 lanes) -> packed (sp2, sn2) staged in smem ----
    if (!half) {
        int other_node = side ? snid : dnid;

        int co = __popcll(m_oth);
        float lt = 0.f, iat_o = 0.f, riat_o = 0.f;
        if (m_oth) {
            int jf = __ffsll((long long)m_oth) - 1;
            int jl = 63 - __clzll((long long)m_oth);
            lt     = s_t[os][jl];
            iat_o  = s_avg[os][jf];
            riat_o = s_rec[os][jf];
        }

        float f0 = (float)n;
        float f1 = (float)co;
        float f2 = (myid == other_node) ? 1.f : 0.f;
        float f3 = (co > 0) ? 1.f : 0.f;
        float f4 = (co > 0) ? __fdividef(f0, f1 + EPSQ) : 0.f;
        float rcy_self  = cur_t - myt;
        float rcy_other = cur_t - lt;
        float f5 = (rcy_self > EPSQ) ? __fdividef(rcy_other, rcy_self + EPSQ) : 0.f;
        float f6 = (iat_o  > EPSQ) ? __fdividef(my_avg, iat_o  + EPSQ) : 0.f;
        float f7 = (riat_o > EPSQ) ? __fdividef(my_rec, riat_o + EPSQ) : 0.f;
        if (myid == 0) { f0 = f1 = f2 = f3 = f4 = f5 = f6 = f7 = 0.f; }

        float sp = fmaxf(f0,0.f)+fmaxf(f1,0.f)+fmaxf(f2,0.f)+fmaxf(f3,0.f)
                 + fmaxf(f4,0.f)+fmaxf(f5,0.f)+fmaxf(f6,0.f)+fmaxf(f7,0.f);
        float sn = fminf(f0,0.f)+fminf(f1,0.f)+fminf(f2,0.f)+fminf(f3,0.f)
                 + fminf(f4,0.f)+fminf(f5,0.f)+fminf(f6,0.f)+fminf(f7,0.f);

        ulonglong2 s2;
        s2.x = pk2(sp, sp);
        s2.y = pk2(sn, sn);
        s_S[pos] = s2;                  // STS.128 into own warp's range

        if (!fast) {
            float* fp = &s_feat[side][i][0];
            fp[0]=f0; fp[1]=f1; fp[2]=f2; fp[3]=f3;
            fp[4]=f4; fp[5]=f5; fp[6]=f6; fp[7]=f7;
        }
    }
    __syncwarp();   // s_S rows for this warp written by its own even lanes

    if (fast) {
        // ---- per-warp store of its own 16 rows; 1 LDS.128/row scalar fetch ----
        const int w    = tid >> 5;          // 0..7
        const int lane = tid & 31;
        const int sdw  = w >> 2;
        const int lb   = (w & 3) << 4;

        const ulonglong2 vvp = __ldg((const ulonglong2*)g_Vp + lane);
        const ulonglong2 vvn = __ldg((const ulonglong2*)g_Vn + lane);
        const ulonglong2 vbb = __ldg((const ulonglong2*)g_Vb + lane);

        const ulonglong2* srow = &s_S[w * 16];
        ulonglong2* out2 = (ulonglong2*)out +
            (((size_t)sdw * B + b) * LQ + lb) * (DQ / 4);
        #pragma unroll
        for (int r = 0; r < 16; ++r) {
            ulonglong2 s2 = srow[r];    // LDS.128 broadcast
            ulonglong2 y;
            y.x = fma2(s2.x, vvp.x, fma2(s2.y, vvn.x, vbb.x));
            y.y = fma2(s2.x, vvp.y, fma2(s2.y, vvn.y, vbb.y));
            __stcs(&out2[r * 32 + lane], y);
        }
    } else {
        // ---- general-b1 path (never taken: dataset has b1 == 0) ----
        __syncthreads();
        __shared__ float sW1[DQ], sb1[DQ];
        if (tid < DQ) { sW1[tid] = W1[tid]; sb1[tid] = b1[tid]; }
        __syncthreads();
        const size_t sideStride = (size_t)B * (LQ * DQ);
        for (int wdx = tid; wdx < 2 * LQ * DQ; wdx += 256) {
            int e    = wdx & 127;
            int row  = wdx >> 7;
            int sd   = row >> 6, l = row & 63;
            float y = 8.f * __ldg(&b2[e]);
            #pragma unroll
            for (int f = 0; f < 8; ++f) {
                float fv  = s_feat[sd][l][f];
                float acc = 0.f;
                for (int d = 0; d < DQ; ++d) {
                    float h = fmaxf(fmaf(fv, sW1[d], sb1[d]), 0.f);
                    acc = fmaf(h, __ldg(&W2[d * DQ + e]), acc);
                }
                y += acc;
            }
            out[(size_t)sd * sideStride + (size_t)b * (LQ * DQ) + (size_t)l * DQ + e] = y;
        }
    }
}

// ---------------------------------------------------------------------------
extern "C" void kernel_launch(void* const* d_in, const int* in_sizes, int n_in,
                              void* d_out, int out_size) {
    const int*   src_ids = (const int*)  d_in[0];
    const int*   dst_ids = (const int*)  d_in[1];
    const int*   src_nid = (const int*)  d_in[2];
    const int*   dst_nid = (const int*)  d_in[3];
    const float* itimes  = (const float*)d_in[4];
    const float* src_t   = (const float*)d_in[5];
    const float* dst_t   = (const float*)d_in[6];
    const float* W1      = (const float*)d_in[7];
    const float* b1      = (const float*)d_in[8];
    const float* W2      = (const float*)d_in[9];
    const float* b2      = (const float*)d_in[10];
    float* out = (float*)d_out;
    int B = in_sizes[2];  // src_node_ids count

    prep_kernel<<<4, 256>>>(W1, b1, W2, b2);
    lpe_main_kernel<<<B, 256>>>(src_ids, dst_ids, src_nid, dst_nid,
                                itimes, src_t, dst_t,
                                W1, b1, W2, b2, out, B);
}